// round 4
// baseline (speedup 1.0000x reference)
#include <cuda_runtime.h>

// Problem shape (fixed by the reference)
#define BB 64
#define SS 2048
#define DD 256
#define TOTROWS (BB * SS)     // 131072 flat (b,s) rows
#define GRIDX 608             // 152 SMs x occ 4 -> exactly one wave on GB300
#define BATCH 8               // explicit in-flight float4 loads per thread

// Global scratch (statically zero-initialized; reset by finalizer each call so
// graph replays see a clean state).
__device__ float    g_sum [BB * DD];
__device__ unsigned g_maxo[BB * DD];   // order-preserving uint encoding; 0 < f2o(any float)
__device__ float    g_cnt [BB];
__device__ int      g_rows[BB];        // rows accumulated so far for this b

__device__ __forceinline__ float neg_inf() { return __int_as_float(0xff800000); }

// Monotone float <-> uint mapping so atomicMax(unsigned) == float max.
__device__ __forceinline__ unsigned f2o(float f) {
    unsigned u = __float_as_uint(f);
    return (u & 0x80000000u) ? ~u : (u | 0x80000000u);
}
__device__ __forceinline__ float o2f(unsigned u) {
    return __uint_as_float((u & 0x80000000u) ? (u & 0x7fffffffu) : ~u);
}

// Accumulate flat rows [rs, re) (all inside batch b), flush to global
// accumulators, and finalize b if this CTA is the one that completes it.
// Called with a CTA-uniform range; contains __syncthreads.
__device__ __forceinline__ void process_range(
    const float* __restrict__ feats, const float* __restrict__ mask,
    float* __restrict__ out, int b, int rs, int re,
    int tid, int d4, int sg)
{
    const int n = re - rs;

    float4 sum = make_float4(0.f, 0.f, 0.f, 0.f);
    float4 mx  = make_float4(neg_inf(), neg_inf(), neg_inf(), neg_inf());
    float  cnt = 0.f;

    // Full batches: 32 rows per step (4 sg-rows x BATCH)
    const int nfull = n / (4 * BATCH);
    const float4* __restrict__ p =
        reinterpret_cast<const float4*>(feats) + (size_t)(rs + sg) * 64 + d4;
    const float* __restrict__ mp = mask + rs + sg;

    for (int bi = 0; bi < nfull; ++bi) {
        float  mbuf[BATCH];
        float4 fbuf[BATCH];
#pragma unroll
        for (int j = 0; j < BATCH; ++j) mbuf[j] = __ldca(mp + j * 4);
#pragma unroll
        for (int j = 0; j < BATCH; ++j) fbuf[j] = __ldcs(p + j * 4 * 64);
#pragma unroll
        for (int j = 0; j < BATCH; ++j) {
            const float  m = mbuf[j];
            const float4 f = fbuf[j];
            const bool   v = (m > 0.f);
            cnt += m;
            sum.x += f.x * m;  sum.y += f.y * m;
            sum.z += f.z * m;  sum.w += f.w * m;
            mx.x = fmaxf(mx.x, v ? f.x : neg_inf());
            mx.y = fmaxf(mx.y, v ? f.y : neg_inf());
            mx.z = fmaxf(mx.z, v ? f.z : neg_inf());
            mx.w = fmaxf(mx.w, v ? f.w : neg_inf());
        }
        mp += 4 * BATCH;
        p  += (size_t)4 * BATCH * 64;
    }

    // Remainder rows (< 32), predicated per sg-lane
    for (int r = rs + nfull * 4 * BATCH + sg; r < re; r += 4) {
        const float  m = __ldca(mask + r);
        const float4 f = __ldcs(reinterpret_cast<const float4*>(feats) +
                                (size_t)r * 64 + d4);
        const bool   v = (m > 0.f);
        cnt += m;
        sum.x += f.x * m;  sum.y += f.y * m;
        sum.z += f.z * m;  sum.w += f.w * m;
        mx.x = fmaxf(mx.x, v ? f.x : neg_inf());
        mx.y = fmaxf(mx.y, v ? f.y : neg_inf());
        mx.z = fmaxf(mx.z, v ? f.z : neg_inf());
        mx.w = fmaxf(mx.w, v ? f.w : neg_inf());
    }

    // CTA-level reduce: 4 sg-groups -> 1 (64 float4 lanes remain)
    __shared__ float4 s_sum[256];
    __shared__ float4 s_max[256];
    __shared__ float  s_cnt[4];
    s_sum[tid] = sum;
    s_max[tid] = mx;
    if (d4 == 0) s_cnt[sg] = cnt;
    __syncthreads();

    if (tid < 64) {
        float4 a = s_sum[tid];
        float4 m = s_max[tid];
#pragma unroll
        for (int k = 1; k < 4; ++k) {
            float4 a2 = s_sum[tid + 64 * k];
            float4 m2 = s_max[tid + 64 * k];
            a.x += a2.x; a.y += a2.y; a.z += a2.z; a.w += a2.w;
            m.x = fmaxf(m.x, m2.x); m.y = fmaxf(m.y, m2.y);
            m.z = fmaxf(m.z, m2.z); m.w = fmaxf(m.w, m2.w);
        }
        const int dbase = b * DD + tid * 4;
        atomicAdd(&g_sum[dbase + 0], a.x);
        atomicAdd(&g_sum[dbase + 1], a.y);
        atomicAdd(&g_sum[dbase + 2], a.z);
        atomicAdd(&g_sum[dbase + 3], a.w);
        atomicMax(&g_maxo[dbase + 0], f2o(m.x));
        atomicMax(&g_maxo[dbase + 1], f2o(m.y));
        atomicMax(&g_maxo[dbase + 2], f2o(m.z));
        atomicMax(&g_maxo[dbase + 3], f2o(m.w));
        if (tid == 0)
            atomicAdd(&g_cnt[b], s_cnt[0] + s_cnt[1] + s_cnt[2] + s_cnt[3]);
    }

    // Order our REDGs before the row-arrival counter; the CTA whose add
    // completes b (reaches SS rows) finalizes it.
    __threadfence();
    __syncthreads();
    __shared__ int s_last;
    if (tid == 0) {
        int prev = atomicAdd(&g_rows[b], n);
        s_last = (prev + n == SS);
    }
    __syncthreads();

    if (s_last) {
        const int d = tid;  // 0..255
        float    fsum = __ldcg(&g_sum[b * DD + d]);
        unsigned mo   = __ldcg(&g_maxo[b * DD + d]);
        float    fcnt = __ldcg(&g_cnt[b]);
        out[(size_t)b * (2 * DD) + d]      = o2f(mo);
        out[(size_t)b * (2 * DD) + DD + d] = fsum / fcnt;
        // Reset scratch for the next graph replay
        __stcg(&g_sum[b * DD + d], 0.f);
        __stcg(&g_maxo[b * DD + d], 0u);
        if (tid == 0) {
            __stcg(&g_cnt[b], 0.f);
            __stcg(&g_rows[b], 0);
        }
    }
    __syncthreads();   // protect smem reuse across calls
}

// One wave of GRIDX CTAs; CTA c owns a contiguous, balanced flat-row range.
__global__ void __launch_bounds__(256, 4)
pool_onewave(const float* __restrict__ feats,
             const float* __restrict__ mask,
             float* __restrict__ out) {
    const int c   = blockIdx.x;
    const int tid = threadIdx.x;
    const int d4  = tid & 63;
    const int sg  = tid >> 6;

    const int R0    = TOTROWS / GRIDX;          // 215
    const int rem   = TOTROWS % GRIDX;          // 352
    const int start = c * R0 + min(c, rem);
    const int nrows = R0 + (c < rem ? 1 : 0);
    const int end   = start + nrows;

    // A CTA range (<=216 rows) spans at most 2 batches (each b is 2048 rows).
    const int b0     = start / SS;
    const int b0_end = min(end, (b0 + 1) * SS);
    process_range(feats, mask, out, b0, start, b0_end, tid, d4, sg);
    if (b0_end < end)
        process_range(feats, mask, out, b0 + 1, b0_end, end, tid, d4, sg);
}

extern "C" void kernel_launch(void* const* d_in, const int* in_sizes, int n_in,
                              void* d_out, int out_size) {
    const float* feats = (const float*)d_in[0];
    const float* mask  = (const float*)d_in[1];
    float* out = (float*)d_out;

    pool_onewave<<<GRIDX, 256>>>(feats, mask, out);
}